// round 6
// baseline (speedup 1.0000x reference)
#include <cuda_runtime.h>

// lagrangian_ode_func: out[i] = { x[i].z, x[i].w,
//                                 -(k1*x0 + k2*(x0-x1)), k2*(x0-x1) }
// FINAL: HBM-roofline streaming kernel. 256 MiB total traffic (irreducible)
// at ~5.9 TB/s = GB300 mixed read/write stream ceiling (~74% of spec).
// 4 float4 rows/thread, front-batched loads (MLP=4), evict-first hints.
// Verified invariant across MLP/occupancy/grid/TPB/cache-policy sweeps
// (R1-R5): kernel dur 36.2-38.0 us in all configs -> memory-controller bound.

#define TPB 256
#define RPT 4

__global__ void __launch_bounds__(TPB)
lagr_ode_kernel(const float4* __restrict__ x,
                const float* __restrict__ k1p,
                const float* __restrict__ k2p,
                float4* __restrict__ out)
{
    const unsigned base = blockIdx.x * (TPB * RPT) + threadIdx.x;
    const float k1 = __ldg(k1p);
    const float k2 = __ldg(k2p);

    // Front-batched independent loads -> MLP=4 per thread
    float4 v[RPT];
#pragma unroll
    for (int j = 0; j < RPT; j++)
        v[j] = __ldcs(&x[base + j * TPB]);

#pragma unroll
    for (int j = 0; j < RPT; j++) {
        const float d = k2 * (v[j].x - v[j].y);   // k2*(q0-q1)
        float4 r;
        r.x = v[j].z;                              // qd0
        r.y = v[j].w;                              // qd1
        r.z = -(k1 * v[j].x + d);                  // qdd0
        r.w = d;                                   // qdd1
        __stcs(&out[base + j * TPB], r);
    }
}

extern "C" void kernel_launch(void* const* d_in, const int* in_sizes, int n_in,
                              void* d_out, int out_size)
{
    // Inputs (metadata order): t [1], x [B*4], k1 [1], k2 [1]
    const float4* x  = (const float4*)d_in[1];
    const float*  k1 = (const float*)d_in[2];
    const float*  k2 = (const float*)d_in[3];
    float4* out = (float4*)d_out;

    const int rows = in_sizes[1] / 4;              // 8388608
    const int blocks = rows / (TPB * RPT);         // 8192, exact

    lagr_ode_kernel<<<blocks, TPB>>>(x, k1, k2, out);
}

// round 7
// speedup vs baseline: 1.0007x; 1.0007x over previous
#include <cuda_runtime.h>

// lagrangian_ode_func: out[i] = { x.z, x.w, -(k1*x0 + k2*(x0-x1)), k2*(x0-x1) }
// Probe: RPT=8 front-batched loads (deepest per-warp MLP), evict-first hints.
// Everything else held at the R2 roofline configuration.

#define TPB 256
#define RPT 8

__global__ void __launch_bounds__(TPB)
lagr_ode_kernel(const float4* __restrict__ x,
                const float* __restrict__ k1p,
                const float* __restrict__ k2p,
                float4* __restrict__ out)
{
    const unsigned base = blockIdx.x * (TPB * RPT) + threadIdx.x;
    const float k1 = __ldg(k1p);
    const float k2 = __ldg(k2p);

    // Front-batched independent loads -> MLP=8 per thread
    float4 v[RPT];
#pragma unroll
    for (int j = 0; j < RPT; j++)
        v[j] = __ldcs(&x[base + j * TPB]);

#pragma unroll
    for (int j = 0; j < RPT; j++) {
        const float d = k2 * (v[j].x - v[j].y);   // k2*(q0-q1)
        float4 r;
        r.x = v[j].z;                              // qd0
        r.y = v[j].w;                              // qd1
        r.z = -(k1 * v[j].x + d);                  // qdd0
        r.w = d;                                   // qdd1
        __stcs(&out[base + j * TPB], r);
    }
}

extern "C" void kernel_launch(void* const* d_in, const int* in_sizes, int n_in,
                              void* d_out, int out_size)
{
    // Inputs (metadata order): t [1], x [B*4], k1 [1], k2 [1]
    const float4* x  = (const float4*)d_in[1];
    const float*  k1 = (const float*)d_in[2];
    const float*  k2 = (const float*)d_in[3];
    float4* out = (float4*)d_out;

    const int rows = in_sizes[1] / 4;              // 8388608
    const int blocks = rows / (TPB * RPT);         // 4096, exact

    lagr_ode_kernel<<<blocks, TPB>>>(x, k1, k2, out);
}